// round 8
// baseline (speedup 1.0000x reference)
#include <cuda_runtime.h>

#define NBLK 128
#define NTHR 256
#define Bc   64
#define Tc   1024
#define DINc 12
#define Hc   256
#define NCc  17

typedef unsigned long long u64;

// ---------------- static device scratch (no allocations allowed) ----------------
__device__ float g_xT[Tc * DINc * Bc];        // x transposed: [t][k][b]   (3 MB)
__device__ float g_out0[(size_t)Tc * 512 * Bc]; // layer-0 output [t][k][b] (128 MB)
__device__ float g_hbuf[2 * 2 * Hc * Bc];     // [dir][parity][j][b]       (512 KB)
__device__ float g_pooled[512 * Bc];          // [k][b]                    (128 KB)
__device__ int g_barcnt;                       // returns to 0 after each barrier
__device__ volatile unsigned g_sense;          // monotone sense, read at launch start

// ---------------- helpers ----------------
__device__ __forceinline__ u64 pk2(float v) {
    u64 r; asm("mov.b64 %0, {%1, %2};" : "=l"(r) : "f"(v), "f"(v)); return r;
}
__device__ __forceinline__ void fma2(u64 &a, u64 x, u64 w) {
    asm("fma.rn.f32x2 %0, %1, %2, %0;" : "+l"(a) : "l"(x), "l"(w));
}
__device__ __forceinline__ float2 up2(u64 v) {
    float2 f; asm("mov.b64 {%0, %1}, %2;" : "=f"(f.x), "=f"(f.y) : "l"(v)); return f;
}
__device__ __forceinline__ float sigm_(float x) { return 1.0f / (1.0f + __expf(-x)); }
__device__ __forceinline__ float tanh_(float x) {
    float e = __expf(-2.0f * fabsf(x));
    float r = (1.0f - e) / (1.0f + e);
    return x >= 0.f ? r : -r;
}

// Sense-reversing global barrier. All NBLK blocks are co-resident (1 per SM).
// Counter self-resets to 0; sense persists across launches and is read at start.
__device__ __forceinline__ void gbar(unsigned &sense) {
    __syncthreads();
    unsigned s = sense + 1u;
    if (threadIdx.x == 0) {
        __threadfence();
        if (atomicAdd(&g_barcnt, 1) == NBLK - 1) {
            g_barcnt = 0;
            __threadfence();
            g_sense = s;
        } else {
            while (g_sense != s) { }
        }
    }
    sense = s;
    __syncthreads();
}

// ---------------- one bidirectional-LSTM phase (fused input projection) ----------------
// Block gb owns: dir = gb>>6, 4 hidden units ub..ub+3 of that direction.
// Gate rows (local r = gate*4 + u): 16 rows of W, staged transposed in shared.
// Per step: gates[16][64] = ws^T(klen x 16) . in(klen x 64), in = concat(x_t, h_prev).
template <bool PH1>
__device__ void run_phase(
    int dir, int ub, int tid,
    const float *__restrict__ inbase, int klin,
    const float *__restrict__ w_ih, const float *__restrict__ w_hh,
    const float *__restrict__ b_ih, const float *__restrict__ b_hh,
    float *ws, float *stage, float *gates, float *cst, float *bias,
    unsigned &sense, float &pool)
{
    const int klen = klin + Hc;

    // Stage weights transposed: ws[k*16 + r]
    for (int idx = tid; idx < klen * 16; idx += NTHR) {
        int k = idx >> 4, r = idx & 15;
        int grow = (r >> 2) * Hc + ub + (r & 3);   // gate*256 + unit
        float v;
        if (k < klin) v = w_ih[(size_t)(dir * 1024 + grow) * klin + k];
        else          v = w_hh[(size_t)(dir * 1024 + grow) * Hc + (k - klin)];
        ws[idx] = v;
    }
    if (tid < 16) {
        int r = tid;
        int grow = (r >> 2) * Hc + ub + (r & 3);
        bias[r] = b_ih[dir * 1024 + grow] + b_hh[dir * 1024 + grow];
    }
    // Zero cell state + this block's slice of h parity-0 buffer
    for (int idx = tid; idx < 4 * Bc; idx += NTHR) {
        cst[idx] = 0.f;
        int u = idx >> 6, b = idx & 63;
        g_hbuf[((dir * 2 + 0) * Hc + ub + u) * Bc + b] = 0.f;
    }
    __threadfence();
    gbar(sense);   // weights/zeros (and caller's global-scratch writes) visible chip-wide

    const int w    = tid >> 5;      // warp = k-segment (stride 8)
    const int lane = tid & 31;
    const int rg   = lane >> 3;     // row-group: rows rg*4..rg*4+3
    const int bg   = lane & 7;      // batch-group: batches bg*8..bg*8+7

    for (int s = 0; s < Tc; s++) {
        const int t   = dir ? (Tc - 1 - s) : s;
        const int par = s & 1;

        u64 acc[16];
        #pragma unroll
        for (int i = 0; i < 16; i++) acc[i] = 0ull;

        const float *hsrc = g_hbuf + (dir * 2 + par) * Hc * Bc;
        const float *xsrc = inbase + (size_t)t * klin * Bc;

        const int nch = (klen + 127) >> 7;
        for (int c = 0; c < nch; c++) {
            const int kb = c << 7;
            int kl = klen - kb; if (kl > 128) kl = 128;
            __syncthreads();
            // stage chunk [kl][64] into shared (coalesced float4, L1-bypassed)
            for (int idx = tid; idx < kl * 16; idx += NTHR) {
                int kk = idx >> 4, b4 = idx & 15;
                int k = kb + kk;
                float4 v;
                if (k < klin) v = __ldcg((const float4 *)(xsrc + (size_t)k * Bc + b4 * 4));
                else          v = __ldcg((const float4 *)(hsrc + (size_t)(k - klin) * Bc + b4 * 4));
                *((float4 *)(stage + kk * Bc) + b4) = v;
            }
            __syncthreads();
            // compute: each warp handles k = w, w+8, ... within the chunk
            const float *wsk = ws + kb * 16;
            for (int k = w; k < kl; k += 8) {
                float4 wv = *(const float4 *)(wsk + k * 16 + rg * 4);
                const float *ap = stage + k * Bc + bg * 8;
                ulonglong2 A0 = *(const ulonglong2 *)(ap);
                ulonglong2 A1 = *(const ulonglong2 *)(ap + 4);
                u64 w0 = pk2(wv.x), w1 = pk2(wv.y), w2 = pk2(wv.z), w3 = pk2(wv.w);
                fma2(acc[0],  A0.x, w0); fma2(acc[1],  A0.y, w0);
                fma2(acc[2],  A1.x, w0); fma2(acc[3],  A1.y, w0);
                fma2(acc[4],  A0.x, w1); fma2(acc[5],  A0.y, w1);
                fma2(acc[6],  A1.x, w1); fma2(acc[7],  A1.y, w1);
                fma2(acc[8],  A0.x, w2); fma2(acc[9],  A0.y, w2);
                fma2(acc[10], A1.x, w2); fma2(acc[11], A1.y, w2);
                fma2(acc[12], A0.x, w3); fma2(acc[13], A0.y, w3);
                fma2(acc[14], A1.x, w3); fma2(acc[15], A1.y, w3);
            }
        }
        __syncthreads();
        // 8-way k-segment reduction (partials alias the stage buffer: 4096 u64 = 32KB)
        u64 *red = (u64 *)stage;
        #pragma unroll
        for (int i = 0; i < 16; i++) red[tid * 16 + i] = acc[i];
        __syncthreads();
        for (int o = tid; o < 512; o += NTHR) {          // 16 rows x 32 batch-pairs
            int r = o >> 5, bp = o & 31;
            int ln = (r >> 2) * 8 + (bp >> 2);
            int i  = (r & 3) * 4 + (bp & 3);
            float2 sc = make_float2(bias[r], bias[r]);
            #pragma unroll
            for (int ks = 0; ks < 8; ks++) {
                float2 v = up2(red[(ks * 32 + ln) * 16 + i]);
                sc.x += v.x; sc.y += v.y;
            }
            *(float2 *)(gates + r * Bc + bp * 2) = sc;
        }
        __syncthreads();
        // pointwise LSTM cell update: one thread per (unit, batch)
        {
            int u = tid >> 6, b = tid & 63;
            float gi = gates[(0 * 4 + u) * Bc + b];
            float gf = gates[(1 * 4 + u) * Bc + b];
            float gg = gates[(2 * 4 + u) * Bc + b];
            float go = gates[(3 * 4 + u) * Bc + b];
            float cc = cst[u * Bc + b];
            cc = sigm_(gf) * cc + sigm_(gi) * tanh_(gg);
            float hh = sigm_(go) * tanh_(cc);
            cst[u * Bc + b] = cc;
            g_hbuf[((dir * 2 + (par ^ 1)) * Hc + ub + u) * Bc + b] = hh;
            if (!PH1) g_out0[((size_t)t * 512 + dir * Hc + ub + u) * Bc + b] = hh;
            else      pool += hh;
        }
        __threadfence();
        gbar(sense);
    }
}

// ---------------- main persistent kernel ----------------
__global__ void __launch_bounds__(NTHR, 1) bilstm_kernel(
    const float *__restrict__ x,
    const float *__restrict__ w_ih0, const float *__restrict__ w_hh0,
    const float *__restrict__ b_ih0, const float *__restrict__ b_hh0,
    const float *__restrict__ w_ih1, const float *__restrict__ w_hh1,
    const float *__restrict__ b_ih1, const float *__restrict__ b_hh1,
    const float *__restrict__ fc_w, const float *__restrict__ fc_b,
    float *__restrict__ out)
{
    extern __shared__ float sm[];
    float *ws    = sm;              // 12288 floats (48KB): weights transposed
    float *stage = sm + 12288;      //  8192 floats (32KB): act chunk / reduction
    float *gates = sm + 20480;      //  1024 floats (4KB)
    float *cst   = sm + 21504;      //   256 floats (1KB)
    float *bias  = sm + 21760;      //    16 floats

    const int tid = threadIdx.x;
    const int gb  = blockIdx.x;
    const int dir = gb >> 6;
    const int ub  = (gb & 63) * 4;

    unsigned sense = g_sense;   // safe: first flip happens only after all blocks arrived

    // transpose x -> g_xT[t][k][b]
    for (int i = gb * NTHR + tid; i < Tc * DINc * Bc; i += NBLK * NTHR) {
        int b = i & 63;
        int j = i >> 6;
        int k = j % DINc;
        int t = j / DINc;
        g_xT[i] = x[((size_t)b * Tc + t) * DINc + k];
    }
    __threadfence();

    float pool = 0.f;
    run_phase<false>(dir, ub, tid, g_xT,  DINc, w_ih0, w_hh0, b_ih0, b_hh0,
                     ws, stage, gates, cst, bias, sense, pool);
    run_phase<true >(dir, ub, tid, g_out0, 512, w_ih1, w_hh1, b_ih1, b_hh1,
                     ws, stage, gates, cst, bias, sense, pool);

    // mean-pool write: thread -> (unit u, batch b), matches pointwise ownership
    {
        int u = tid >> 6, b = tid & 63;
        g_pooled[(dir * Hc + ub + u) * Bc + b] = pool * (1.0f / (float)Tc);
    }
    __threadfence();
    gbar(sense);

    // final FC on block 0 (tiny: 64x17 dots of length 512)
    if (gb == 0) {
        for (int o = tid; o < Bc * NCc; o += NTHR) {
            int b = o / NCc, c = o % NCc;
            float sacc = fc_b[c];
            for (int k = 0; k < 512; k++)
                sacc += __ldcg(&g_pooled[k * Bc + b]) * fc_w[c * 512 + k];
            out[b * NCc + c] = sacc;
        }
    }
}

// ---------------- launch ----------------
extern "C" void kernel_launch(void *const *d_in, const int *in_sizes, int n_in,
                              void *d_out, int out_size)
{
    (void)in_sizes; (void)n_in; (void)out_size;
    const float *x     = (const float *)d_in[0];
    const float *w_ih0 = (const float *)d_in[1];
    const float *w_hh0 = (const float *)d_in[2];
    const float *b_ih0 = (const float *)d_in[3];
    const float *b_hh0 = (const float *)d_in[4];
    const float *w_ih1 = (const float *)d_in[5];
    const float *w_hh1 = (const float *)d_in[6];
    const float *b_ih1 = (const float *)d_in[7];
    const float *b_hh1 = (const float *)d_in[8];
    const float *fc_w  = (const float *)d_in[9];
    const float *fc_b  = (const float *)d_in[10];
    float *out = (float *)d_out;

    // 132KB dynamic smem: holds all buffers and forces 1 block/SM so all 128
    // blocks are co-resident (required by the software global barrier).
    const int smem = 132 * 1024;
    cudaFuncSetAttribute(bilstm_kernel, cudaFuncAttributeMaxDynamicSharedMemorySize, smem);

    bilstm_kernel<<<NBLK, NTHR, smem>>>(x, w_ih0, w_hh0, b_ih0, b_hh0,
                                        w_ih1, w_hh1, b_ih1, b_hh1,
                                        fc_w, fc_b, out);
}

// round 10
// speedup vs baseline: 1.1936x; 1.1936x over previous
#include <cuda_runtime.h>

#define NBLK 128
#define NTHR 256
#define Bc   64
#define Tc   1024
#define Hc   256
#define DINc 12
#define NCc  17

typedef unsigned long long u64;

// ---------------- static device scratch (no allocations allowed) ----------------
__device__ float g_xT[Tc * DINc * Bc];           // x transposed [t][k][b]
__device__ float g_out0[(size_t)Tc * 512 * Bc];  // layer-0 out  [t][k][b]  (128 MB)
__device__ float g_hbuf[2 * 2 * Hc * Bc];        // [dir][parity][j][b]
__device__ float g_pooled[512 * Bc];             // [k][b]
__device__ float g_fcst[4 * NCc * Bc];           // FC k-split partials
// Barrier state: per-dir (64 blocks each) + full (128 blocks). 128B-padded.
__device__ unsigned g_cnt_d[2 * 32];             // counters, reset each round
__device__ volatile unsigned g_sn_d[2 * 32];     // completed-round counts (monotone)
__device__ unsigned g_cnt_f;
__device__ volatile unsigned g_sn_f;

// ---------------- helpers ----------------
__device__ __forceinline__ u64 pk2(float v) {
    u64 r; asm("mov.b64 %0, {%1, %2};" : "=l"(r) : "f"(v), "f"(v)); return r;
}
__device__ __forceinline__ void fma2(u64 &a, u64 x, u64 w) {
    asm("fma.rn.f32x2 %0, %1, %2, %0;" : "+l"(a) : "l"(x), "l"(w));
}
__device__ __forceinline__ float2 up2(u64 v) {
    float2 f; asm("mov.b64 {%0, %1}, %2;" : "=f"(f.x), "=f"(f.y) : "l"(v)); return f;
}
__device__ __forceinline__ float sigm_(float x) { return 1.0f / (1.0f + __expf(-x)); }
__device__ __forceinline__ float tanh_(float x) {
    float e = __expf(-2.0f * fabsf(x));
    float r = (1.0f - e) / (1.0f + e);
    return x >= 0.f ? r : -r;
}

// Fused sense-style barrier (round-7 proven algorithm, parameterized instance).
// Caller must issue __threadfence() from ALL threads before calling (release).
// Counter self-resets; sense is a monotone completed-round count; local mirror
// `ls` is initialized from the global at kernel start.
__device__ __forceinline__ void gbar(unsigned *cnt, volatile unsigned *gs,
                                     unsigned &ls, unsigned n) {
    __syncthreads();
    unsigned tgt = ls + 1u;
    if (threadIdx.x == 0) {
        __threadfence();
        if (atomicAdd(cnt, 1u) == n - 1u) {
            *cnt = 0u;
            __threadfence();
            *gs = tgt;
        } else {
            while ((int)(*gs - tgt) < 0) { }
        }
    }
    ls = tgt;
    __syncthreads();
}

__device__ __forceinline__ void mac16(u64 *acc, float4 wv, ulonglong2 A0, ulonglong2 A1) {
    u64 w0 = pk2(wv.x), w1 = pk2(wv.y), w2 = pk2(wv.z), w3 = pk2(wv.w);
    fma2(acc[0],  A0.x, w0); fma2(acc[1],  A0.y, w0);
    fma2(acc[2],  A1.x, w0); fma2(acc[3],  A1.y, w0);
    fma2(acc[4],  A0.x, w1); fma2(acc[5],  A0.y, w1);
    fma2(acc[6],  A1.x, w1); fma2(acc[7],  A1.y, w1);
    fma2(acc[8],  A0.x, w2); fma2(acc[9],  A0.y, w2);
    fma2(acc[10], A1.x, w2); fma2(acc[11], A1.y, w2);
    fma2(acc[12], A0.x, w3); fma2(acc[13], A0.y, w3);
    fma2(acc[14], A1.x, w3); fma2(acc[15], A1.y, w3);
}

// ---------------- one bidirectional-LSTM phase (fused input projection) ----------------
// Block gb: dir = gb>>6, owns 4 hidden units ub..ub+3 (16 gate rows, staged
// transposed in shared). Per step: gates[16][64] = ws^T . concat(x_t, h_prev),
// activations read directly from L2 via __ldcg. One per-dir barrier per step.
template <int KLIN, bool PH1>
__device__ void run_phase(
    int dir, int ub, int tid,
    const float *__restrict__ inbase,
    const float *__restrict__ w_ih, const float *__restrict__ w_hh,
    const float *__restrict__ b_ih, const float *__restrict__ b_hh,
    float *ws, u64 *red, float *gates, float *cst, float *bias,
    unsigned &sd, unsigned &sf, float &pool)
{
    constexpr int KLEN = KLIN + Hc;

    // Stage weights transposed: ws[k*16 + r]  (coalesced global reads)
    for (int idx = tid; idx < 16 * KLEN; idx += NTHR) {
        int r = idx / KLEN, k = idx - r * KLEN;
        int grow = (r >> 2) * Hc + ub + (r & 3);       // gate*256 + unit
        float v = (k < KLIN) ? w_ih[(size_t)(dir * 1024 + grow) * KLIN + k]
                             : w_hh[(size_t)(dir * 1024 + grow) * Hc + (k - KLIN)];
        ws[k * 16 + r] = v;
    }
    if (tid < 16) {
        int grow = (tid >> 2) * Hc + ub + (tid & 3);
        bias[tid] = b_ih[dir * 1024 + grow] + b_hh[dir * 1024 + grow];
    }
    // Zero cell state + this block's slice of h parity-0 buffer
    for (int idx = tid; idx < 4 * Bc; idx += NTHR) {
        cst[idx] = 0.f;
        int u = idx >> 6, b = idx & 63;
        g_hbuf[((dir * 2 + 0) * Hc + ub + u) * Bc + b] = 0.f;
    }
    __threadfence();
    gbar(&g_cnt_f, &g_sn_f, sf, NBLK);   // full: prev phase outputs + inits visible

    const int w    = tid >> 5;      // warp = k-segment (stride 8)
    const int lane = tid & 31;
    const int rg   = lane >> 3;     // rows rg*4..rg*4+3
    const int bg   = lane & 7;      // batches bg*8..bg*8+7
    const int uu   = tid >> 6;      // pointwise ownership
    const int bb   = tid & 63;

    for (int s = 0; s < Tc; s++) {
        const int t = dir ? (Tc - 1 - s) : s;

        u64 acc[16];
        #pragma unroll
        for (int i = 0; i < 16; i++) acc[i] = 0ull;

        // ---- x-part (input projection, fused) ----
        const float *xsrc = inbase + (size_t)t * KLIN * Bc;
        #pragma unroll 4
        for (int k = w; k < KLIN; k += 8) {
            float4 wv = *(const float4 *)(ws + k * 16 + rg * 4);
            const ulonglong2 *ap = (const ulonglong2 *)(xsrc + k * Bc + bg * 8);
            ulonglong2 A0 = __ldcg(ap), A1 = __ldcg(ap + 1);
            mac16(acc, wv, A0, A1);
        }

        // ---- h-part (h(s-1) is globally visible: barrier at end of step s-1) ----
        const float *hsrc = g_hbuf + (dir * 2 + (s & 1)) * Hc * Bc;
        #pragma unroll 4
        for (int k = w; k < Hc; k += 8) {
            float4 wv = *(const float4 *)(ws + (KLIN + k) * 16 + rg * 4);
            const ulonglong2 *ap = (const ulonglong2 *)(hsrc + k * Bc + bg * 8);
            ulonglong2 A0 = __ldcg(ap), A1 = __ldcg(ap + 1);
            mac16(acc, wv, A0, A1);
        }

        // ---- 8-way k-segment reduction (stride-17 padding: conflict-free) ----
        #pragma unroll
        for (int i = 0; i < 16; i++) red[tid * 17 + i] = acc[i];
        __syncthreads();
        #pragma unroll
        for (int o = tid; o < 512; o += NTHR) {   // 16 rows x 32 batch-pairs
            int r = o >> 5, bp = o & 31;
            int ln = (r >> 2) * 8 + (bp >> 2);
            int i  = (r & 3) * 4 + (bp & 3);
            float2 sc = make_float2(bias[r], bias[r]);
            #pragma unroll
            for (int ks = 0; ks < 8; ks++) {
                float2 v = up2(red[(ks * 32 + ln) * 17 + i]);
                sc.x += v.x; sc.y += v.y;
            }
            *(float2 *)(gates + r * Bc + bp * 2) = sc;
        }
        __syncthreads();

        // ---- pointwise LSTM cell update: one thread per (unit, batch) ----
        {
            float gi = gates[(0 * 4 + uu) * Bc + bb];
            float gf = gates[(1 * 4 + uu) * Bc + bb];
            float gg = gates[(2 * 4 + uu) * Bc + bb];
            float go = gates[(3 * 4 + uu) * Bc + bb];
            float cc = cst[uu * Bc + bb];
            cc = sigm_(gf) * cc + sigm_(gi) * tanh_(gg);
            float hh = sigm_(go) * tanh_(cc);
            cst[uu * Bc + bb] = cc;
            g_hbuf[((dir * 2 + ((s & 1) ^ 1)) * Hc + ub + uu) * Bc + bb] = hh;
            if (!PH1) g_out0[((size_t)t * 512 + dir * Hc + ub + uu) * Bc + bb] = hh;
            else      pool += hh;
        }
        __threadfence();   // release own h/out0 stores
        gbar(&g_cnt_d[dir * 32], &g_sn_d[dir * 32], sd, 64);   // per-dir step barrier
    }
}

// ---------------- main persistent kernel ----------------
__global__ void __launch_bounds__(NTHR, 1) bilstm_kernel(
    const float *__restrict__ x,
    const float *__restrict__ w_ih0, const float *__restrict__ w_hh0,
    const float *__restrict__ b_ih0, const float *__restrict__ b_hh0,
    const float *__restrict__ w_ih1, const float *__restrict__ w_hh1,
    const float *__restrict__ b_ih1, const float *__restrict__ b_hh1,
    const float *__restrict__ fc_w, const float *__restrict__ fc_b,
    float *__restrict__ out)
{
    extern __shared__ float sm[];
    float *ws    = sm;                         // 12288 floats (48KB)
    u64   *red   = (u64 *)(sm + 12288);        // 4352 u64 (34KB, stride-17 padded)
    float *gates = sm + 12288 + 8704;          // 1024 floats
    float *cst   = gates + 1024;               // 256 floats
    float *bias  = cst + 256;                  // 16 floats

    const int tid = threadIdx.x;
    const int gb  = blockIdx.x;
    const int dir = gb >> 6;
    const int ub  = (gb & 63) * 4;

    // Monotone barrier round mirrors (persist across graph replays)
    unsigned sd = g_sn_d[dir * 32];
    unsigned sf = g_sn_f;

    // transpose x -> g_xT[t][k][b]
    for (int i = gb * NTHR + tid; i < Tc * DINc * Bc; i += NBLK * NTHR) {
        int b = i & 63;
        int j = i >> 6;
        int k = j % DINc;
        int t = j / DINc;
        g_xT[i] = x[((size_t)b * Tc + t) * DINc + k];
    }
    __threadfence();

    float pool = 0.f;
    run_phase<DINc, false>(dir, ub, tid, g_xT,  w_ih0, w_hh0, b_ih0, b_hh0,
                           ws, red, gates, cst, bias, sd, sf, pool);
    run_phase<512,  true >(dir, ub, tid, g_out0, w_ih1, w_hh1, b_ih1, b_hh1,
                           ws, red, gates, cst, bias, sd, sf, pool);

    // mean-pool write (matches pointwise ownership)
    {
        int u = tid >> 6, b = tid & 63;
        g_pooled[(dir * Hc + ub + u) * Bc + b] = pool * (1.0f / (float)Tc);
    }
    __threadfence();
    gbar(&g_cnt_f, &g_sn_f, sf, NBLK);

    // final FC on block 0 (64x17 dots of length 512, k-split 4 ways)
    if (gb == 0) {
        for (int i = tid; i < NCc * 512; i += NTHR) ws[i] = fc_w[i];
        __syncthreads();
        float *redf = (float *)red;
        int b = tid & 63, kq = tid >> 6;
        float part[NCc];
        #pragma unroll
        for (int c = 0; c < NCc; c++) part[c] = 0.f;
        for (int k = kq * 128; k < kq * 128 + 128; k++) {
            float pv = __ldcg(&g_pooled[k * Bc + b]);
            #pragma unroll
            for (int c = 0; c < NCc; c++) part[c] += pv * ws[c * 512 + k];
        }
        #pragma unroll
        for (int c = 0; c < NCc; c++) redf[(kq * NCc + c) * Bc + b] = part[c];
        __syncthreads();
        for (int o = tid; o < Bc * NCc; o += NTHR) {
            int c = o >> 6, b2 = o & 63;
            float s_ = fc_b[c];
            #pragma unroll
            for (int q = 0; q < 4; q++) s_ += redf[(q * NCc + c) * Bc + b2];
            out[b2 * NCc + c] = s_;
        }
    }
}

// ---------------- launch ----------------
extern "C" void kernel_launch(void *const *d_in, const int *in_sizes, int n_in,
                              void *d_out, int out_size)
{
    (void)in_sizes; (void)n_in; (void)out_size;
    const float *x     = (const float *)d_in[0];
    const float *w_ih0 = (const float *)d_in[1];
    const float *w_hh0 = (const float *)d_in[2];
    const float *b_ih0 = (const float *)d_in[3];
    const float *b_hh0 = (const float *)d_in[4];
    const float *w_ih1 = (const float *)d_in[5];
    const float *w_hh1 = (const float *)d_in[6];
    const float *b_ih1 = (const float *)d_in[7];
    const float *b_hh1 = (const float *)d_in[8];
    const float *fc_w  = (const float *)d_in[9];
    const float *fc_b  = (const float *)d_in[10];
    float *out = (float *)d_out;

    // 89,152 B dynamic smem. Grid 128 <= 148 SMs -> all blocks co-resident.
    const int smem = (12288 + 8704 * 2 + 1024 + 256 + 16) * 4;
    cudaFuncSetAttribute(bilstm_kernel, cudaFuncAttributeMaxDynamicSharedMemorySize, smem);

    bilstm_kernel<<<NBLK, NTHR, smem>>>(x, w_ih0, w_hh0, b_ih0, b_hh0,
                                        w_ih1, w_hh1, b_ih1, b_hh1,
                                        fc_w, fc_b, out);
}

// round 11
// speedup vs baseline: 1.4081x; 1.1798x over previous
#include <cuda_runtime.h>

#define NBLK 128
#define NTHR 512
#define Bc   64
#define Tc   1024
#define Hc   256
#define DINc 12
#define NCc  17

typedef unsigned long long u64;

// ---------------- static device scratch (no allocations allowed) ----------------
__device__ float g_xT[Tc * DINc * Bc];           // x transposed [t][k][b]
__device__ float g_out0[(size_t)Tc * 512 * Bc];  // layer-0 out  [t][k][b]  (128 MB)
__device__ float g_hbuf[2 * 2 * Hc * Bc];        // [dir][parity][j][b]
__device__ float g_pooled[512 * Bc];             // [k][b]
// Barrier state: per-dir (64 blocks each) + full (128 blocks). Padded apart.
__device__ unsigned g_cnt_d[2 * 32];             // counters, self-reset each round
__device__ volatile unsigned g_sn_d[2 * 32];     // completed-round counts (monotone)
__device__ unsigned g_cnt_f;
__device__ volatile unsigned g_sn_f;

// ---------------- helpers ----------------
__device__ __forceinline__ u64 pk2(float v) {
    u64 r; asm("mov.b64 %0, {%1, %2};" : "=l"(r) : "f"(v), "f"(v)); return r;
}
__device__ __forceinline__ void fma2(u64 &a, u64 x, u64 w) {
    asm("fma.rn.f32x2 %0, %1, %2, %0;" : "+l"(a) : "l"(x), "l"(w));
}
__device__ __forceinline__ float2 up2(u64 v) {
    float2 f; asm("mov.b64 {%0, %1}, %2;" : "=f"(f.x), "=f"(f.y) : "l"(v)); return f;
}
__device__ __forceinline__ float sigm_(float x) { return 1.0f / (1.0f + __expf(-x)); }
__device__ __forceinline__ float tanh_(float x) {
    float e = __expf(-2.0f * fabsf(x));
    float r = (1.0f - e) / (1.0f + e);
    return x >= 0.f ? r : -r;
}

// Fused sense-style barrier (proven round-7/9 algorithm).
// Callers issue __threadfence() before this (release of their global stores).
__device__ __forceinline__ void gbar(unsigned *cnt, volatile unsigned *gs,
                                     unsigned &ls, unsigned n) {
    __syncthreads();
    unsigned tgt = ls + 1u;
    if (threadIdx.x == 0) {
        __threadfence();
        if (atomicAdd(cnt, 1u) == n - 1u) {
            *cnt = 0u;
            __threadfence();
            *gs = tgt;
        } else {
            while ((int)(*gs - tgt) < 0) { }
        }
    }
    ls = tgt;
    __syncthreads();
}

// acc[rr*2 + j] += A_j * w_rr   (4 rows x 4 batches, batches as 2 u64 pairs)
__device__ __forceinline__ void mac8(u64 *acc, float4 wv, ulonglong2 A) {
    u64 w0 = pk2(wv.x), w1 = pk2(wv.y), w2 = pk2(wv.z), w3 = pk2(wv.w);
    fma2(acc[0], A.x, w0); fma2(acc[1], A.y, w0);
    fma2(acc[2], A.x, w1); fma2(acc[3], A.y, w1);
    fma2(acc[4], A.x, w2); fma2(acc[5], A.y, w2);
    fma2(acc[6], A.x, w3); fma2(acc[7], A.y, w3);
}

// ---------------- one bidirectional-LSTM phase (fused input projection) ----------------
// Block gb: dir = gb>>6, owns 4 hidden units ub..ub+3 (16 gate rows, staged
// transposed in shared). 16 warps = 8 k-segments x 2 batch-halves.
// Per lane: 4 rows x 4 batches (8 u64 accs), one LDG.128 of activations per k.
template <int KLIN, bool PH1>
__device__ void run_phase(
    int dir, int ub, int tid,
    const float *__restrict__ inbase,
    const float *__restrict__ w_ih, const float *__restrict__ w_hh,
    const float *__restrict__ b_ih, const float *__restrict__ b_hh,
    float *ws, u64 *red, float *gates, float *cst, float *bias,
    unsigned &sd, unsigned &sf, float &pool)
{
    constexpr int KLEN = KLIN + Hc;

    // Stage weights transposed: ws[k*16 + r]  (coalesced global reads)
    for (int idx = tid; idx < 16 * KLEN; idx += NTHR) {
        int r = idx / KLEN, k = idx - r * KLEN;
        int grow = (r >> 2) * Hc + ub + (r & 3);       // gate*256 + unit
        float v = (k < KLIN) ? w_ih[(size_t)(dir * 1024 + grow) * KLIN + k]
                             : w_hh[(size_t)(dir * 1024 + grow) * Hc + (k - KLIN)];
        ws[k * 16 + r] = v;
    }
    if (tid < 16) {
        int grow = (tid >> 2) * Hc + ub + (tid & 3);
        bias[tid] = b_ih[dir * 1024 + grow] + b_hh[dir * 1024 + grow];
    }
    // Zero cell state + this block's slice of h parity-0 buffer
    if (tid < 4 * Bc) {
        cst[tid] = 0.f;
        int u = tid >> 6, b = tid & 63;
        g_hbuf[((dir * 2 + 0) * Hc + ub + u) * Bc + b] = 0.f;
    }
    __threadfence();
    gbar(&g_cnt_f, &g_sn_f, sf, NBLK);   // full: prev phase outputs + inits visible

    const int lane = tid & 31;
    const int ks   = (tid >> 5) & 7;     // k-segment (stride 8)
    const int bh   = tid >> 8;           // batch half (0/1)
    const int rg   = lane >> 3;          // rows rg*4..rg*4+3
    const int bg   = lane & 7;           // 4 batches at bh*32 + bg*4
    const int boff = bh * 32 + bg * 4;

    for (int s = 0; s < Tc; s++) {
        const int t = dir ? (Tc - 1 - s) : s;

        u64 acc[8];
        #pragma unroll
        for (int i = 0; i < 8; i++) acc[i] = 0ull;

        // ---- x-part (input projection, fused) ----
        const float *xsrc = inbase + (size_t)t * KLIN * Bc;
        #pragma unroll 4
        for (int k = ks; k < KLIN; k += 8) {
            float4 wv = *(const float4 *)(ws + k * 16 + rg * 4);
            ulonglong2 A = __ldcg((const ulonglong2 *)(xsrc + k * Bc + boff));
            mac8(acc, wv, A);
        }

        // ---- h-part (h(s-1) globally visible: barrier at end of step s-1) ----
        const float *hsrc = g_hbuf + (dir * 2 + (s & 1)) * Hc * Bc;
        #pragma unroll 4
        for (int k = ks; k < Hc; k += 8) {
            float4 wv = *(const float4 *)(ws + (KLIN + k) * 16 + rg * 4);
            ulonglong2 A = __ldcg((const ulonglong2 *)(hsrc + k * Bc + boff));
            mac8(acc, wv, A);
        }

        // ---- 8-way k-segment reduction (stride-9 u64 padding per thread) ----
        #pragma unroll
        for (int i = 0; i < 8; i++) red[tid * 9 + i] = acc[i];
        __syncthreads();
        {   // one output (row r, batch-pair bp) per thread
            int o = tid;
            int r = o >> 5, bp = o & 31;
            int bh2 = bp >> 4, p = bp & 15;
            int bg2 = p >> 1, j = p & 1;
            int lane2 = (r >> 2) * 8 + bg2;
            int i = (r & 3) * 2 + j;
            float2 sc = make_float2(bias[r], bias[r]);
            #pragma unroll
            for (int q = 0; q < 8; q++) {
                float2 v = up2(red[(((bh2 * 8 + q) * 32) + lane2) * 9 + i]);
                sc.x += v.x; sc.y += v.y;
            }
            *(float2 *)(gates + r * Bc + bp * 2) = sc;
        }
        __syncthreads();

        // ---- pointwise LSTM cell update: thread (unit, batch), tid<256 ----
        if (tid < 256) {
            int uu = tid >> 6, bb = tid & 63;
            float gi = gates[(0 * 4 + uu) * Bc + bb];
            float gf = gates[(1 * 4 + uu) * Bc + bb];
            float gg = gates[(2 * 4 + uu) * Bc + bb];
            float go = gates[(3 * 4 + uu) * Bc + bb];
            float cc = cst[uu * Bc + bb];
            cc = sigm_(gf) * cc + sigm_(gi) * tanh_(gg);
            float hh = sigm_(go) * tanh_(cc);
            cst[uu * Bc + bb] = cc;
            g_hbuf[((dir * 2 + ((s & 1) ^ 1)) * Hc + ub + uu) * Bc + bb] = hh;
            if (!PH1) g_out0[((size_t)t * 512 + dir * Hc + ub + uu) * Bc + bb] = hh;
            else      pool += hh;
        }
        __threadfence();   // release own h/out0 stores
        gbar(&g_cnt_d[dir * 32], &g_sn_d[dir * 32], sd, 64);   // per-dir step barrier
    }
}

// ---------------- main persistent kernel ----------------
__global__ void __launch_bounds__(NTHR, 1) bilstm_kernel(
    const float *__restrict__ x,
    const float *__restrict__ w_ih0, const float *__restrict__ w_hh0,
    const float *__restrict__ b_ih0, const float *__restrict__ b_hh0,
    const float *__restrict__ w_ih1, const float *__restrict__ w_hh1,
    const float *__restrict__ b_ih1, const float *__restrict__ b_hh1,
    const float *__restrict__ fc_w, const float *__restrict__ fc_b,
    float *__restrict__ out)
{
    extern __shared__ float sm[];
    float *ws    = sm;                         // 12288 floats (48KB)
    u64   *red   = (u64 *)(sm + 12288);        // 4608 u64 (36KB, stride-9/thread)
    float *gates = sm + 12288 + 9216;          // 1024 floats
    float *cst   = gates + 1024;               // 256 floats
    float *bias  = cst + 256;                  // 16 floats

    const int tid = threadIdx.x;
    const int gb  = blockIdx.x;
    const int dir = gb >> 6;
    const int ub  = (gb & 63) * 4;

    // Monotone barrier round mirrors (persist across graph replays)
    unsigned sd = g_sn_d[dir * 32];
    unsigned sf = g_sn_f;

    // transpose x -> g_xT[t][k][b]
    for (int i = gb * NTHR + tid; i < Tc * DINc * Bc; i += NBLK * NTHR) {
        int b = i & 63;
        int j = i >> 6;
        int k = j % DINc;
        int t = j / DINc;
        g_xT[i] = x[((size_t)b * Tc + t) * DINc + k];
    }
    __threadfence();

    float pool = 0.f;
    run_phase<DINc, false>(dir, ub, tid, g_xT,  w_ih0, w_hh0, b_ih0, b_hh0,
                           ws, red, gates, cst, bias, sd, sf, pool);
    run_phase<512,  true >(dir, ub, tid, g_out0, w_ih1, w_hh1, b_ih1, b_hh1,
                           ws, red, gates, cst, bias, sd, sf, pool);

    // mean-pool write (matches pointwise ownership)
    if (tid < 256) {
        int u = tid >> 6, b = tid & 63;
        g_pooled[(dir * Hc + ub + u) * Bc + b] = pool * (1.0f / (float)Tc);
    }
    __threadfence();
    gbar(&g_cnt_f, &g_sn_f, sf, NBLK);

    // final FC on block 0 (64x17 dots of length 512, k-split 8 ways)
    if (gb == 0) {
        for (int i = tid; i < NCc * 512; i += NTHR) ws[i] = fc_w[i];
        __syncthreads();
        float *redf = (float *)red;
        int b = tid & 63, kq = tid >> 6;           // 8 segments of 64 k
        float part[NCc];
        #pragma unroll
        for (int c = 0; c < NCc; c++) part[c] = 0.f;
        for (int k = kq * 64; k < kq * 64 + 64; k++) {
            float pv = __ldcg(&g_pooled[k * Bc + b]);
            #pragma unroll
            for (int c = 0; c < NCc; c++) part[c] += pv * ws[c * 512 + k];
        }
        #pragma unroll
        for (int c = 0; c < NCc; c++) redf[(kq * NCc + c) * Bc + b] = part[c];
        __syncthreads();
        for (int o = tid; o < Bc * NCc; o += NTHR) {
            int c = o >> 6, b2 = o & 63;
            float s_ = fc_b[c];
            #pragma unroll
            for (int q = 0; q < 8; q++) s_ += redf[(q * NCc + c) * Bc + b2];
            out[b2 * NCc + c] = s_;
        }
    }
}

// ---------------- launch ----------------
extern "C" void kernel_launch(void *const *d_in, const int *in_sizes, int n_in,
                              void *d_out, int out_size)
{
    (void)in_sizes; (void)n_in; (void)out_size;
    const float *x     = (const float *)d_in[0];
    const float *w_ih0 = (const float *)d_in[1];
    const float *w_hh0 = (const float *)d_in[2];
    const float *b_ih0 = (const float *)d_in[3];
    const float *b_hh0 = (const float *)d_in[4];
    const float *w_ih1 = (const float *)d_in[5];
    const float *w_hh1 = (const float *)d_in[6];
    const float *b_ih1 = (const float *)d_in[7];
    const float *b_hh1 = (const float *)d_in[8];
    const float *fc_w  = (const float *)d_in[9];
    const float *fc_b  = (const float *)d_in[10];
    float *out = (float *)d_out;

    // 120KB dynamic smem (91KB used, padded): forces 1 block/SM so all 128
    // blocks are co-resident (required by the software global barriers).
    const int smem = 120 * 1024;
    cudaFuncSetAttribute(bilstm_kernel, cudaFuncAttributeMaxDynamicSharedMemorySize, smem);

    bilstm_kernel<<<NBLK, NTHR, smem>>>(x, w_ih0, w_hh0, b_ih0, b_hh0,
                                        w_ih1, w_hh1, b_ih1, b_hh1,
                                        fc_w, fc_b, out);
}